// round 15
// baseline (speedup 1.0000x reference)
#include <cuda_runtime.h>
#include <math.h>
#include <stdint.h>

#define T_STEPS 512
#define BATCH   64
#define NINP_D  512
#define NHID_D  1024
#define NGATE   4096   // 4*NHID
#define NCTA_R  128
#define NWORK   20     // spare-SM GEMM worker CTAs

// ---------------- scratch (device globals; no runtime allocation) ----------
__device__ float g_xw_enc[(size_t)T_STEPS * BATCH * NGATE]; // 512 MB
__device__ float g_xw_dec[(size_t)T_STEPS * BATCH * NGATE]; // 512 MB
__device__ float g_in_r[(size_t)T_STEPS * BATCH * NINP_D];  // rna-rounded input (64 MB)
__device__ float g_wih_r[2][(size_t)NGATE * NINP_D];        // rna-rounded W_ih (2x8 MB)
__device__ float g_h[2][BATCH * NHID_D];                    // h [b][u], tf32-rounded, ping-pong
__device__ unsigned g_arr1[128];   // group counters (stride 8 -> 32B apart)
__device__ unsigned g_root;
__device__ unsigned g_release;
__device__ unsigned g_gemm_done;   // dec-GEMM worker completions

// ---------------- generic helpers ------------------------------------------
__device__ __forceinline__ void cp_async16(unsigned s, const void* g) {
    asm volatile("cp.async.cg.shared.global [%0], [%1], 16;" :: "r"(s), "l"(g));
}
__device__ __forceinline__ void cp_commit() { asm volatile("cp.async.commit_group;"); }
__device__ __forceinline__ void cp_wait0()  { asm volatile("cp.async.wait_group 0;" ::: "memory"); }
__device__ __forceinline__ void cp_wait1()  { asm volatile("cp.async.wait_group 1;" ::: "memory"); }

__device__ __forceinline__ uint32_t tf32r_bits(float x) {
    uint32_t u; asm("cvt.rna.tf32.f32 %0, %1;" : "=r"(u) : "f"(x)); return u;
}
__device__ __forceinline__ float tf32r(float x) { return __uint_as_float(tf32r_bits(x)); }

// tf32 mma.sync (sm_80+, arch-portable): D[16x8] += A[16x8] * B[8x8]
__device__ __forceinline__ void mma_tf32(float& c0, float& c1, float& c2, float& c3,
                                         uint32_t a0, uint32_t a1, uint32_t a2, uint32_t a3,
                                         uint32_t b0, uint32_t b1) {
    asm("mma.sync.aligned.m16n8k8.row.col.f32.tf32.tf32.f32 "
        "{%0,%1,%2,%3}, {%4,%5,%6,%7}, {%8,%9}, {%0,%1,%2,%3};"
        : "+f"(c0), "+f"(c1), "+f"(c2), "+f"(c3)
        : "r"(a0), "r"(a1), "r"(a2), "r"(a3), "r"(b0), "r"(b1));
}

// ---------------- init ------------------------------------------------------
__global__ void init_state() {
    int i = blockIdx.x * blockDim.x + threadIdx.x;
    if (i == 0) { g_root = 0; g_release = 0; g_gemm_done = 0; }
    if (i < 128) g_arr1[i] = 0;
    if (i < BATCH * NHID_D) { g_h[0][i] = 0.f; g_h[1][i] = 0.f; }
}

// ---------------- rna tf32 pre-round ---------------------------------------
__global__ __launch_bounds__(256) void round_tf32_k(const float* __restrict__ src,
                                                    float* __restrict__ dst, int n4) {
    int i = blockIdx.x * blockDim.x + threadIdx.x;
    if (i < n4) {
        float4 v = __ldg((const float4*)src + i);
        float4 o;
        o.x = tf32r(v.x); o.y = tf32r(v.y); o.z = tf32r(v.z); o.w = tf32r(v.w);
        ((float4*)dst)[i] = o;
    }
}

// ---------------- xW GEMM tile body (validated R8 gemm core) ----------------
// One 128x128 output tile of C = A @ W^T + bias, K=512. Uses dynsm.
#define AST 36
#define GBUF (128 * AST)

extern __shared__ float dynsm[];

__device__ __forceinline__ void gemm_tile(const float* __restrict__ A,
                                          const float* __restrict__ W,
                                          const float* __restrict__ bias,
                                          float* __restrict__ C,
                                          size_t m0, size_t n0) {
    unsigned abase = (unsigned)__cvta_generic_to_shared(dynsm);
    unsigned bbase = abase + 2u * GBUF * 4u;
    const uint32_t* Asw = (const uint32_t*)dynsm;
    const uint32_t* Bsw = Asw + 2 * GBUF;

    int t = threadIdx.x, lane = t & 31, wid = t >> 5;
    int gid = lane >> 2, tid = lane & 3;
    int wm = wid & 3, wn = wid >> 2;

    float acc[2][8][4];
    #pragma unroll
    for (int mt = 0; mt < 2; mt++)
        #pragma unroll
        for (int nt = 0; nt < 8; nt++)
            #pragma unroll
            for (int r = 0; r < 4; r++) acc[mt][nt][r] = 0.f;

#define GFILL(kb, buf) do {                                                     \
        _Pragma("unroll")                                                       \
        for (int i_ = 0; i_ < 4; i_++) {                                        \
            int id_ = t + 256 * i_;                                             \
            int row_ = id_ >> 3, q_ = id_ & 7;                                  \
            cp_async16(abase + (unsigned)((buf) * GBUF + row_ * AST + q_ * 4) * 4, \
                       A + (m0 + row_) * NINP_D + (kb) * 32 + q_ * 4);          \
            cp_async16(bbase + (unsigned)((buf) * GBUF + row_ * AST + q_ * 4) * 4, \
                       W + (n0 + row_) * NINP_D + (kb) * 32 + q_ * 4);          \
        }                                                                       \
        cp_commit();                                                            \
    } while (0)

    GFILL(0, 0);
    #pragma unroll 1
    for (int kb = 0; kb < NINP_D / 32; kb++) {
        if (kb < NINP_D / 32 - 1) { GFILL(kb + 1, (kb + 1) & 1); cp_wait1(); }
        else cp_wait0();
        __syncthreads();
        const uint32_t* Ap = Asw + (kb & 1) * GBUF;
        const uint32_t* Bp = Bsw + (kb & 1) * GBUF;
        #pragma unroll
        for (int kk = 0; kk < 4; kk++) {
            int kl = kk * 8;
            uint32_t a[2][4], b[8][2];
            #pragma unroll
            for (int mt = 0; mt < 2; mt++) {
                int rb = wm * 32 + mt * 16;
                a[mt][0] = Ap[(rb + gid) * AST + kl + tid];
                a[mt][1] = Ap[(rb + gid + 8) * AST + kl + tid];
                a[mt][2] = Ap[(rb + gid) * AST + kl + tid + 4];
                a[mt][3] = Ap[(rb + gid + 8) * AST + kl + tid + 4];
            }
            #pragma unroll
            for (int nt = 0; nt < 8; nt++) {
                int rn = wn * 64 + nt * 8;
                b[nt][0] = Bp[(rn + gid) * AST + kl + tid];
                b[nt][1] = Bp[(rn + gid) * AST + kl + tid + 4];
            }
            #pragma unroll
            for (int mt = 0; mt < 2; mt++)
                #pragma unroll
                for (int nt = 0; nt < 8; nt++)
                    mma_tf32(acc[mt][nt][0], acc[mt][nt][1],
                             acc[mt][nt][2], acc[mt][nt][3],
                             a[mt][0], a[mt][1], a[mt][2], a[mt][3],
                             b[nt][0], b[nt][1]);
        }
        __syncthreads();
    }
#undef GFILL

    #pragma unroll
    for (int nt = 0; nt < 8; nt++) {
        int col = (int)n0 + wn * 64 + nt * 8 + 2 * tid;
        float2 bv = *(const float2*)&bias[col];
        #pragma unroll
        for (int mt = 0; mt < 2; mt++) {
            int r0 = wm * 32 + mt * 16 + gid;
            *(float2*)&C[(m0 + r0) * NGATE + col] =
                make_float2(acc[mt][nt][0] + bv.x, acc[mt][nt][1] + bv.y);
            *(float2*)&C[(m0 + r0 + 8) * NGATE + col] =
                make_float2(acc[mt][nt][2] + bv.x, acc[mt][nt][3] + bv.y);
        }
    }
}

__global__ __launch_bounds__(256) void gemm_xw_tc(const float* __restrict__ A,
                                                  const float* __restrict__ W,
                                                  const float* __restrict__ bias,
                                                  int which) {
    float* C = which ? g_xw_dec : g_xw_enc;
    gemm_tile(A, W, bias, C, (size_t)blockIdx.y * 128, (size_t)blockIdx.x * 128);
}

// ---------------- two-level grid barrier (R12-validated) ---------------------
__device__ __forceinline__ void barrier_arrive(unsigned target) {
    __threadfence();
    __syncthreads();
    if (threadIdx.x == 0) {
        int grp = blockIdx.x >> 3;
        unsigned prev = atomicAdd(&g_arr1[grp * 8], 1u);
        if (prev == target * 8u - 1u) {
            unsigned pr = atomicAdd(&g_root, 1u);
            if (pr == target * 16u - 1u) atomicExch(&g_release, target);
        }
    }
}
__device__ __forceinline__ void barrier_wait(unsigned target) {
    if (threadIdx.x == 0) {
        while (*(volatile unsigned*)&g_release < target) __nanosleep(32);
        __threadfence();
    }
    __syncthreads();
}

// ---------------- persistent tf32 mma.sync recurrence (R12 core) ------------
// CTAs 0..127: recurrence (byte-identical to R12). CTAs 128..147: dec-xW
// GEMM workers on the otherwise-idle SMs, done before the decoder phase.
#define WST 1028
#define TST 36                    // warp tile row stride (words), ≡4 mod 32
#define TILEW (32 * TST)          // words per warp tile buffer (4608 B)
#define RST 34                    // reduce row stride (words)

__global__ __launch_bounds__(256) void rnn_persist(
        const float* __restrict__ W_enc, const float* __restrict__ W_dec,
        const float* __restrict__ bhh_enc, const float* __restrict__ bhh_dec,
        const float* __restrict__ bih_dec,
        const float* __restrict__ mask, float* __restrict__ out) {
    // ---- spare-SM dec-GEMM workers ----
    if (blockIdx.x >= NCTA_R) {
        int worker = blockIdx.x - NCTA_R;                  // 0..19
        const float* A = g_in_r;
        const float* W = g_wih_r[1];
        #pragma unroll 1
        for (int tile = worker; tile < 32 * 256; tile += NWORK) {
            size_t n0 = (size_t)(tile & 31) * 128;
            size_t m0 = (size_t)(tile >> 5) * 128;
            gemm_tile(A, W, bih_dec, g_xw_dec, m0, n0);
        }
        __threadfence();
        __syncthreads();
        if (threadIdx.x == 0) atomicAdd(&g_gemm_done, 1u);
        return;
    }

    float* wtile = dynsm;                 // [32][WST]
    float* atile = dynsm + 32 * WST;      // [8 warps][2 bufs][32][TST]
    float* red   = atile;                 // overlay: [4][64][RST]
    const uint32_t* wb = (const uint32_t*)wtile;

    int t = threadIdx.x, lane = t & 31, wid = t >> 5;
    int gid = lane >> 2, tid = lane & 3;
    int wm = wid >> 2, wk = wid & 3;
    int u0 = blockIdx.x * 8;
    int eb = t & 63, eup = t >> 6;
    int gu = u0 + 2 * eup;

    // warp-private tile base (smem address space)
    unsigned wtbase = (unsigned)__cvta_generic_to_shared(atile) + (unsigned)(wid * 2 * TILEW) * 4u;
    const uint32_t* wtw = (const uint32_t*)atile + wid * 2 * TILEW;
    int frow = (lane >> 3);               // fill: row group 0..3
    int fseg = (lane & 7);                // fill: 16B segment 0..7

    float creg[2] = {0.f, 0.f};
    float hreg[2] = {0.f, 0.f};
    float breg[4][2];

    for (int gstep = 0; gstep < 2 * T_STEPS; gstep++) {
        int is_dec = gstep >= T_STEPS;
        int step   = gstep & (T_STEPS - 1);
        const float* ht_in  = g_h[gstep & 1];
        float*       ht_out = g_h[(gstep + 1) & 1];
        const float* xw = (is_dec ? g_xw_dec : g_xw_enc) + (size_t)step * BATCH * NGATE;

        // decoder phase gate: dec xW must be fully produced by the workers
        if (gstep == T_STEPS) {
            if (t == 0) {
                while (*(volatile unsigned*)&g_gemm_done < (unsigned)NWORK)
                    __nanosleep(64);
                __threadfence();
            }
            __syncthreads();
        }

        if (step == 0) {
            // W slice -> smem (tf32-rounded). smem row c = g*8+uu.  (validated)
            const float* Wh = is_dec ? W_dec : W_enc;
            int c  = t >> 3;
            int kb = (t & 7) * 128;
            const float* src = Wh + (size_t)((c >> 3) * NHID_D + u0 + (c & 7)) * NHID_D + kb;
            uint32_t* dst = (uint32_t*)(wtile + c * WST + kb);
            #pragma unroll 8
            for (int k = 0; k < 128; k += 4) {
                float4 v = __ldg((const float4*)(src + k));
                uint32_t x0 = tf32r_bits(v.x), x1 = tf32r_bits(v.y);
                uint32_t x2 = tf32r_bits(v.z), x3 = tf32r_bits(v.w);
                asm volatile("st.shared.v4.b32 [%0], {%1,%2,%3,%4};"
                             :: "l"(__cvta_generic_to_shared(dst + k)),
                                "r"(x0), "r"(x1), "r"(x2), "r"(x3));
            }
            #pragma unroll
            for (int g = 0; g < 4; g++) {
                const float* bh = is_dec ? bhh_dec : bhh_enc;
                float2 v = *(const float2*)(bh + g * NHID_D + gu);
                breg[g][0] = v.x; breg[g][1] = v.y;
            }
            __syncthreads();
        }

        // step-static prefetches (no h dependency) -> overlap with barrier wait
        float xv[4][2];
        #pragma unroll
        for (int g = 0; g < 4; g++) {
            float2 v = __ldcg((const float2*)(xw + (size_t)eb * NGATE + g * NHID_D + gu));
            xv[g][0] = v.x; xv[g][1] = v.y;
        }
        float mv = 1.f;
        if (!is_dec) mv = __ldg(&mask[(size_t)step * BATCH + eb]);

        barrier_wait((unsigned)gstep);

        float acc[2][4][4];
        #pragma unroll
        for (int mt = 0; mt < 2; mt++)
            #pragma unroll
            for (int nt = 0; nt < 4; nt++)
                #pragma unroll
                for (int r = 0; r < 4; r++) acc[mt][nt][r] = 0.f;

        // warp-private fill of own 32x32 tile for chunk ch into buffer buf
#define FILL_OWN(ch, buf) do {                                                   \
        const float* hsrc_ = ht_in + (size_t)(wm * 32) * NHID_D + (ch) * 128     \
                           + wk * 32 + fseg * 4;                                 \
        unsigned d0_ = wtbase + (unsigned)((buf) * TILEW + frow * TST + fseg * 4) * 4u; \
        _Pragma("unroll")                                                        \
        for (int i_ = 0; i_ < 8; i_++)                                           \
            cp_async16(d0_ + (unsigned)(i_ * 4 * TST) * 4u,                      \
                       hsrc_ + (size_t)(i_ * 4 + frow) * NHID_D);                \
        cp_commit();                                                             \
    } while (0)

        FILL_OWN(0, 0);
        #pragma unroll 1
        for (int c = 0; c < 8; c++) {
            if (c < 7) { FILL_OWN(c + 1, (c + 1) & 1); cp_wait1(); }
            else cp_wait0();
            __syncwarp();
            const uint32_t* tw = wtw + (c & 1) * TILEW;
            #pragma unroll
            for (int kk = 0; kk < 4; kk++) {
                int kl = kk * 8;                      // k within warp's 32-col tile
                int kgw = c * 128 + wk * 32 + kl;     // k in W tile
                uint32_t a[2][4], bf[4][2];
                #pragma unroll
                for (int mt = 0; mt < 2; mt++) {
                    int rl = mt * 16;                 // local row base
                    a[mt][0] = tw[(rl + gid) * TST + kl + tid];
                    a[mt][1] = tw[(rl + gid + 8) * TST + kl + tid];
                    a[mt][2] = tw[(rl + gid) * TST + kl + tid + 4];
                    a[mt][3] = tw[(rl + gid + 8) * TST + kl + tid + 4];
                }
                #pragma unroll
                for (int nt = 0; nt < 4; nt++) {
                    bf[nt][0] = wb[(nt * 8 + gid) * WST + kgw + tid];
                    bf[nt][1] = wb[(nt * 8 + gid) * WST + kgw + tid + 4];
                }
                #pragma unroll
                for (int mt = 0; mt < 2; mt++)
                    #pragma unroll
                    for (int nt = 0; nt < 4; nt++)
                        mma_tf32(acc[mt][nt][0], acc[mt][nt][1],
                                 acc[mt][nt][2], acc[mt][nt][3],
                                 a[mt][0], a[mt][1], a[mt][2], a[mt][3],
                                 bf[nt][0], bf[nt][1]);
            }
        }
#undef FILL_OWN

        __syncthreads();              // all warps' mma reads done before red overlay

        // store k-partials (overlay on A-tile region)
        #pragma unroll
        for (int mt = 0; mt < 2; mt++) {
            int r0 = wm * 32 + mt * 16 + gid;
            #pragma unroll
            for (int nt = 0; nt < 4; nt++) {
                int cc = nt * 8 + 2 * tid;
                *(float2*)&red[(wk * 64 + r0) * RST + cc] =
                    make_float2(acc[mt][nt][0], acc[mt][nt][1]);
                *(float2*)&red[(wk * 64 + r0 + 8) * RST + cc] =
                    make_float2(acc[mt][nt][2], acc[mt][nt][3]);
            }
        }
        __syncthreads();

        // 4-way reduce + LSTM epilogue: thread owns cells (eb, gu), (eb, gu+1)
        float gate[4][2];
        #pragma unroll
        for (int g = 0; g < 4; g++) {
            float2 s = make_float2(0.f, 0.f);
            #pragma unroll
            for (int k4 = 0; k4 < 4; k4++) {
                float2 v = *(const float2*)&red[(k4 * 64 + eb) * RST + g * 8 + 2 * eup];
                s.x += v.x; s.y += v.y;
            }
            gate[g][0] = s.x + xv[g][0] + breg[g][0];
            gate[g][1] = s.y + xv[g][1] + breg[g][1];
        }
        float hro[2], ho[2];
        #pragma unroll
        for (int j = 0; j < 2; j++) {
            float gi = 1.f / (1.f + expf(-gate[0][j]));
            float gf = 1.f / (1.f + expf(-gate[1][j]));
            float gc = tanhf(gate[2][j]);
            float go = 1.f / (1.f + expf(-gate[3][j]));
            float cn = fmaf(gf, creg[j], gi * gc);
            float hn = go * tanhf(cn);
            if (!is_dec && mv == 0.f) { hn = hreg[j]; cn = creg[j]; }
            creg[j] = cn;
            float hr = tf32r(hn);
            hreg[j] = hr;
            hro[j] = hr;
            ho[j]  = hn;
        }
        __stcg((float2*)(ht_out + (size_t)eb * NHID_D + gu), make_float2(hro[0], hro[1]));

        barrier_arrive((unsigned)(gstep + 1));   // h published; out stores overlap peers

        if (is_dec)
            *(float2*)(out + ((size_t)step * BATCH + eb) * NHID_D + gu) =
                make_float2(ho[0], ho[1]);
    }
}

// ---------------- launch ----------------------------------------------------
extern "C" void kernel_launch(void* const* d_in, const int* in_sizes, int n_in,
                              void* d_out, int out_size) {
    const float* input    = (const float*)d_in[0];  // [512,64,512]
    const float* mask     = (const float*)d_in[1];  // [512,64]
    const float* W_ih_enc = (const float*)d_in[2];  // [4096,512]
    const float* W_hh_enc = (const float*)d_in[3];  // [4096,1024]
    const float* b_ih_enc = (const float*)d_in[4];  // [4096]
    const float* b_hh_enc = (const float*)d_in[5];  // [4096]
    const float* W_ih_dec = (const float*)d_in[6];
    const float* W_hh_dec = (const float*)d_in[7];
    const float* b_ih_dec = (const float*)d_in[8];
    const float* b_hh_dec = (const float*)d_in[9];
    float* out = (float*)d_out;                     // [32768,1024]

    const int gemm_smem = 4 * GBUF * 4;                        // 73,728 B
    const int rnn_smem  = (32 * WST + 8 * 2 * TILEW) * 4;      // 205,312 B
    cudaFuncSetAttribute(gemm_xw_tc, cudaFuncAttributeMaxDynamicSharedMemorySize, gemm_smem);
    cudaFuncSetAttribute(rnn_persist, cudaFuncAttributeMaxDynamicSharedMemorySize, rnn_smem);

    init_state<<<(BATCH * NHID_D + 255) / 256, 256>>>();

    // rna pre-round of GEMM inputs (unbiased tf32)
    float* in_r  = nullptr; float* w0_r = nullptr; float* w1_r = nullptr;
    cudaGetSymbolAddress((void**)&in_r, g_in_r);
    cudaGetSymbolAddress((void**)&w0_r, g_wih_r);
    w1_r = w0_r + (size_t)NGATE * NINP_D;
    const int n4_in = T_STEPS * BATCH * NINP_D / 4;
    const int n4_w  = NGATE * NINP_D / 4;
    round_tf32_k<<<(n4_in + 255) / 256, 256>>>(input, in_r, n4_in);
    round_tf32_k<<<(n4_w + 255) / 256, 256>>>(W_ih_enc, w0_r, n4_w);
    round_tf32_k<<<(n4_w + 255) / 256, 256>>>(W_ih_dec, w1_r, n4_w);

    // encoder xW: full-chip, up front (needed at gstep 0)
    dim3 gg(NGATE / 128, (T_STEPS * BATCH) / 128);
    gemm_xw_tc<<<gg, 256, gemm_smem>>>(in_r, w0_r, b_ih_enc, 0);

    // recurrence (128 CTAs) + dec-xW workers (20 CTAs) on the spare SMs
    rnn_persist<<<NCTA_R + NWORK, 256, rnn_smem>>>(
        W_hh_enc, W_hh_dec, b_hh_enc, b_hh_dec, b_ih_dec, mask, out);
}

// round 16
// speedup vs baseline: 1.0955x; 1.0955x over previous
#include <cuda_runtime.h>
#include <math.h>
#include <stdint.h>

#define T_STEPS 512
#define BATCH   64
#define NINP_D  512
#define NHID_D  1024
#define NGATE   4096   // 4*NHID
#define NCTA_R  128

// ---------------- scratch (device globals; no runtime allocation) ----------
__device__ float g_xw_enc[(size_t)T_STEPS * BATCH * NGATE]; // 512 MB
__device__ float g_xw_dec[(size_t)T_STEPS * BATCH * NGATE]; // 512 MB
__device__ float g_in_r[(size_t)T_STEPS * BATCH * NINP_D];  // rna-rounded input (64 MB)
__device__ float g_wih_r[2][(size_t)NGATE * NINP_D];        // rna-rounded W_ih (2x8 MB)
__device__ float g_h[2][BATCH * NHID_D];                    // h [b][u], tf32-rounded, ping-pong
__device__ unsigned g_arr1[128];      // group arrive counters (stride 8 -> 32B apart)
__device__ unsigned g_root;
__device__ unsigned g_release[128];   // replicated release slots (stride 8 -> per-group line)

// ---------------- generic helpers ------------------------------------------
__device__ __forceinline__ void cp_async16(unsigned s, const void* g) {
    asm volatile("cp.async.cg.shared.global [%0], [%1], 16;" :: "r"(s), "l"(g));
}
__device__ __forceinline__ void cp_commit() { asm volatile("cp.async.commit_group;"); }
__device__ __forceinline__ void cp_wait0()  { asm volatile("cp.async.wait_group 0;" ::: "memory"); }
__device__ __forceinline__ void cp_wait1()  { asm volatile("cp.async.wait_group 1;" ::: "memory"); }

__device__ __forceinline__ uint32_t tf32r_bits(float x) {
    uint32_t u; asm("cvt.rna.tf32.f32 %0, %1;" : "=r"(u) : "f"(x)); return u;
}
__device__ __forceinline__ float tf32r(float x) { return __uint_as_float(tf32r_bits(x)); }

// tf32 mma.sync (sm_80+, arch-portable): D[16x8] += A[16x8] * B[8x8]
__device__ __forceinline__ void mma_tf32(float& c0, float& c1, float& c2, float& c3,
                                         uint32_t a0, uint32_t a1, uint32_t a2, uint32_t a3,
                                         uint32_t b0, uint32_t b1) {
    asm("mma.sync.aligned.m16n8k8.row.col.f32.tf32.tf32.f32 "
        "{%0,%1,%2,%3}, {%4,%5,%6,%7}, {%8,%9}, {%0,%1,%2,%3};"
        : "+f"(c0), "+f"(c1), "+f"(c2), "+f"(c3)
        : "r"(a0), "r"(a1), "r"(a2), "r"(a3), "r"(b0), "r"(b1));
}

// ---------------- init ------------------------------------------------------
__global__ void init_state() {
    int i = blockIdx.x * blockDim.x + threadIdx.x;
    if (i == 0) g_root = 0;
    if (i < 128) { g_arr1[i] = 0; g_release[i] = 0; }
    if (i < BATCH * NHID_D) { g_h[0][i] = 0.f; g_h[1][i] = 0.f; }
}

// ---------------- rna tf32 pre-round ---------------------------------------
__global__ __launch_bounds__(256) void round_tf32_k(const float* __restrict__ src,
                                                    float* __restrict__ dst, int n4) {
    int i = blockIdx.x * blockDim.x + threadIdx.x;
    if (i < n4) {
        float4 v = __ldg((const float4*)src + i);
        float4 o;
        o.x = tf32r(v.x); o.y = tf32r(v.y); o.z = tf32r(v.z); o.w = tf32r(v.w);
        ((float4*)dst)[i] = o;
    }
}

// ---------------- phase 1: xW = input @ W_ih^T + b_ih (tf32 mma.sync) ------
// CTA 128x128, k-chunk 32 dbuf, 8 warps (4m x 2n), warp tile 32x64. (validated)
#define AST 36
#define GBUF (128 * AST)

extern __shared__ float dynsm[];

__global__ __launch_bounds__(256) void gemm_xw_tc(const float* __restrict__ A,
                                                  const float* __restrict__ W,
                                                  const float* __restrict__ bias,
                                                  int which) {
    float* C = which ? g_xw_dec : g_xw_enc;
    unsigned abase = (unsigned)__cvta_generic_to_shared(dynsm);
    unsigned bbase = abase + 2u * GBUF * 4u;
    const uint32_t* Asw = (const uint32_t*)dynsm;
    const uint32_t* Bsw = Asw + 2 * GBUF;

    int t = threadIdx.x, lane = t & 31, wid = t >> 5;
    int gid = lane >> 2, tid = lane & 3;
    int wm = wid & 3, wn = wid >> 2;
    size_t m0 = (size_t)blockIdx.y * 128, n0 = (size_t)blockIdx.x * 128;

    float acc[2][8][4];
    #pragma unroll
    for (int mt = 0; mt < 2; mt++)
        #pragma unroll
        for (int nt = 0; nt < 8; nt++)
            #pragma unroll
            for (int r = 0; r < 4; r++) acc[mt][nt][r] = 0.f;

#define GFILL(kb, buf) do {                                                     \
        _Pragma("unroll")                                                       \
        for (int i_ = 0; i_ < 4; i_++) {                                        \
            int id_ = t + 256 * i_;                                             \
            int row_ = id_ >> 3, q_ = id_ & 7;                                  \
            cp_async16(abase + (unsigned)((buf) * GBUF + row_ * AST + q_ * 4) * 4, \
                       A + (m0 + row_) * NINP_D + (kb) * 32 + q_ * 4);          \
            cp_async16(bbase + (unsigned)((buf) * GBUF + row_ * AST + q_ * 4) * 4, \
                       W + (n0 + row_) * NINP_D + (kb) * 32 + q_ * 4);          \
        }                                                                       \
        cp_commit();                                                            \
    } while (0)

    GFILL(0, 0);
    #pragma unroll 1
    for (int kb = 0; kb < NINP_D / 32; kb++) {
        if (kb < NINP_D / 32 - 1) { GFILL(kb + 1, (kb + 1) & 1); cp_wait1(); }
        else cp_wait0();
        __syncthreads();
        const uint32_t* Ap = Asw + (kb & 1) * GBUF;
        const uint32_t* Bp = Bsw + (kb & 1) * GBUF;
        #pragma unroll
        for (int kk = 0; kk < 4; kk++) {
            int kl = kk * 8;
            uint32_t a[2][4], b[8][2];
            #pragma unroll
            for (int mt = 0; mt < 2; mt++) {
                int rb = wm * 32 + mt * 16;
                a[mt][0] = Ap[(rb + gid) * AST + kl + tid];
                a[mt][1] = Ap[(rb + gid + 8) * AST + kl + tid];
                a[mt][2] = Ap[(rb + gid) * AST + kl + tid + 4];
                a[mt][3] = Ap[(rb + gid + 8) * AST + kl + tid + 4];
            }
            #pragma unroll
            for (int nt = 0; nt < 8; nt++) {
                int rn = wn * 64 + nt * 8;
                b[nt][0] = Bp[(rn + gid) * AST + kl + tid];
                b[nt][1] = Bp[(rn + gid) * AST + kl + tid + 4];
            }
            #pragma unroll
            for (int mt = 0; mt < 2; mt++)
                #pragma unroll
                for (int nt = 0; nt < 8; nt++)
                    mma_tf32(acc[mt][nt][0], acc[mt][nt][1],
                             acc[mt][nt][2], acc[mt][nt][3],
                             a[mt][0], a[mt][1], a[mt][2], a[mt][3],
                             b[nt][0], b[nt][1]);
        }
        __syncthreads();
    }
#undef GFILL

    #pragma unroll
    for (int nt = 0; nt < 8; nt++) {
        int col = (int)n0 + wn * 64 + nt * 8 + 2 * tid;
        float2 bv = *(const float2*)&bias[col];
        #pragma unroll
        for (int mt = 0; mt < 2; mt++) {
            int r0 = wm * 32 + mt * 16 + gid;
            *(float2*)&C[(m0 + r0) * NGATE + col] =
                make_float2(acc[mt][nt][0] + bv.x, acc[mt][nt][1] + bv.y);
            *(float2*)&C[(m0 + r0 + 8) * NGATE + col] =
                make_float2(acc[mt][nt][2] + bv.x, acc[mt][nt][3] + bv.y);
        }
    }
}

// ---------------- two-level grid barrier, replicated release -----------------
// arrive: 8-CTA group counter -> root (validated). release: root writes 16
// per-group slots (32B apart); each CTA polls ONLY its group's slot (8
// sharers/line instead of 128 -> cheaper invalidate + faster wakeup).
__device__ __forceinline__ void barrier_arrive(unsigned target) {
    __threadfence();
    __syncthreads();
    if (threadIdx.x == 0) {
        int grp = blockIdx.x >> 3;
        unsigned prev = atomicAdd(&g_arr1[grp * 8], 1u);
        if (prev == target * 8u - 1u) {
            unsigned pr = atomicAdd(&g_root, 1u);
            if (pr == target * 16u - 1u) {
                #pragma unroll
                for (int g = 0; g < 16; g++)
                    atomicExch(&g_release[g * 8], target);
            }
        }
    }
}
__device__ __forceinline__ void barrier_wait(unsigned target) {
    if (threadIdx.x == 0) {
        volatile unsigned* rel = (volatile unsigned*)&g_release[(blockIdx.x >> 3) * 8];
        while (*rel < target) __nanosleep(32);
        __threadfence();
    }
    __syncthreads();
}

// ---------------- persistent tf32 mma.sync recurrence (R12 core, exact) -----
#define WST 1028
#define TST 36                    // warp tile row stride (words), ≡4 mod 32
#define TILEW (32 * TST)          // words per warp tile buffer (4608 B)
#define RST 34                    // reduce row stride (words)

__global__ __launch_bounds__(256) void rnn_persist(
        const float* __restrict__ W_enc, const float* __restrict__ W_dec,
        const float* __restrict__ bhh_enc, const float* __restrict__ bhh_dec,
        const float* __restrict__ mask, float* __restrict__ out) {
    float* wtile = dynsm;                 // [32][WST]
    float* atile = dynsm + 32 * WST;      // [8 warps][2 bufs][32][TST]
    float* red   = atile;                 // overlay: [4][64][RST]
    const uint32_t* wb = (const uint32_t*)wtile;

    int t = threadIdx.x, lane = t & 31, wid = t >> 5;
    int gid = lane >> 2, tid = lane & 3;
    int wm = wid >> 2, wk = wid & 3;
    int u0 = blockIdx.x * 8;
    int eb = t & 63, eup = t >> 6;
    int gu = u0 + 2 * eup;

    // warp-private tile base (smem address space)
    unsigned wtbase = (unsigned)__cvta_generic_to_shared(atile) + (unsigned)(wid * 2 * TILEW) * 4u;
    const uint32_t* wtw = (const uint32_t*)atile + wid * 2 * TILEW;
    int frow = (lane >> 3);               // fill: row group 0..3
    int fseg = (lane & 7);                // fill: 16B segment 0..7

    float creg[2] = {0.f, 0.f};
    float hreg[2] = {0.f, 0.f};
    float breg[4][2];

    for (int gstep = 0; gstep < 2 * T_STEPS; gstep++) {
        int is_dec = gstep >= T_STEPS;
        int step   = gstep & (T_STEPS - 1);
        const float* ht_in  = g_h[gstep & 1];
        float*       ht_out = g_h[(gstep + 1) & 1];
        const float* xw = (is_dec ? g_xw_dec : g_xw_enc) + (size_t)step * BATCH * NGATE;

        if (step == 0) {
            // W slice -> smem (tf32-rounded). smem row c = g*8+uu.  (validated)
            const float* Wh = is_dec ? W_dec : W_enc;
            int c  = t >> 3;
            int kb = (t & 7) * 128;
            const float* src = Wh + (size_t)((c >> 3) * NHID_D + u0 + (c & 7)) * NHID_D + kb;
            uint32_t* dst = (uint32_t*)(wtile + c * WST + kb);
            #pragma unroll 8
            for (int k = 0; k < 128; k += 4) {
                float4 v = __ldg((const float4*)(src + k));
                uint32_t x0 = tf32r_bits(v.x), x1 = tf32r_bits(v.y);
                uint32_t x2 = tf32r_bits(v.z), x3 = tf32r_bits(v.w);
                asm volatile("st.shared.v4.b32 [%0], {%1,%2,%3,%4};"
                             :: "l"(__cvta_generic_to_shared(dst + k)),
                                "r"(x0), "r"(x1), "r"(x2), "r"(x3));
            }
            #pragma unroll
            for (int g = 0; g < 4; g++) {
                const float* bh = is_dec ? bhh_dec : bhh_enc;
                float2 v = *(const float2*)(bh + g * NHID_D + gu);
                breg[g][0] = v.x; breg[g][1] = v.y;
            }
            __syncthreads();
        }

        // step-static prefetches (no h dependency) -> overlap with barrier wait
        float xv[4][2];
        #pragma unroll
        for (int g = 0; g < 4; g++) {
            float2 v = __ldcg((const float2*)(xw + (size_t)eb * NGATE + g * NHID_D + gu));
            xv[g][0] = v.x; xv[g][1] = v.y;
        }
        float mv = 1.f;
        if (!is_dec) mv = __ldg(&mask[(size_t)step * BATCH + eb]);

        barrier_wait((unsigned)gstep);

        float acc[2][4][4];
        #pragma unroll
        for (int mt = 0; mt < 2; mt++)
            #pragma unroll
            for (int nt = 0; nt < 4; nt++)
                #pragma unroll
                for (int r = 0; r < 4; r++) acc[mt][nt][r] = 0.f;

        // warp-private fill of own 32x32 tile for chunk ch into buffer buf
#define FILL_OWN(ch, buf) do {                                                   \
        const float* hsrc_ = ht_in + (size_t)(wm * 32) * NHID_D + (ch) * 128     \
                           + wk * 32 + fseg * 4;                                 \
        unsigned d0_ = wtbase + (unsigned)((buf) * TILEW + frow * TST + fseg * 4) * 4u; \
        _Pragma("unroll")                                                        \
        for (int i_ = 0; i_ < 8; i_++)                                           \
            cp_async16(d0_ + (unsigned)(i_ * 4 * TST) * 4u,                      \
                       hsrc_ + (size_t)(i_ * 4 + frow) * NHID_D);                \
        cp_commit();                                                             \
    } while (0)

        FILL_OWN(0, 0);
        #pragma unroll 1
        for (int c = 0; c < 8; c++) {
            if (c < 7) { FILL_OWN(c + 1, (c + 1) & 1); cp_wait1(); }
            else cp_wait0();
            __syncwarp();
            const uint32_t* tw = wtw + (c & 1) * TILEW;
            #pragma unroll
            for (int kk = 0; kk < 4; kk++) {
                int kl = kk * 8;                      // k within warp's 32-col tile
                int kgw = c * 128 + wk * 32 + kl;     // k in W tile
                uint32_t a[2][4], bf[4][2];
                #pragma unroll
                for (int mt = 0; mt < 2; mt++) {
                    int rl = mt * 16;                 // local row base
                    a[mt][0] = tw[(rl + gid) * TST + kl + tid];
                    a[mt][1] = tw[(rl + gid + 8) * TST + kl + tid];
                    a[mt][2] = tw[(rl + gid) * TST + kl + tid + 4];
                    a[mt][3] = tw[(rl + gid + 8) * TST + kl + tid + 4];
                }
                #pragma unroll
                for (int nt = 0; nt < 4; nt++) {
                    bf[nt][0] = wb[(nt * 8 + gid) * WST + kgw + tid];
                    bf[nt][1] = wb[(nt * 8 + gid) * WST + kgw + tid + 4];
                }
                #pragma unroll
                for (int mt = 0; mt < 2; mt++)
                    #pragma unroll
                    for (int nt = 0; nt < 4; nt++)
                        mma_tf32(acc[mt][nt][0], acc[mt][nt][1],
                                 acc[mt][nt][2], acc[mt][nt][3],
                                 a[mt][0], a[mt][1], a[mt][2], a[mt][3],
                                 bf[nt][0], bf[nt][1]);
            }
        }
#undef FILL_OWN

        __syncthreads();              // all warps' mma reads done before red overlay

        // store k-partials (overlay on A-tile region)
        #pragma unroll
        for (int mt = 0; mt < 2; mt++) {
            int r0 = wm * 32 + mt * 16 + gid;
            #pragma unroll
            for (int nt = 0; nt < 4; nt++) {
                int cc = nt * 8 + 2 * tid;
                *(float2*)&red[(wk * 64 + r0) * RST + cc] =
                    make_float2(acc[mt][nt][0], acc[mt][nt][1]);
                *(float2*)&red[(wk * 64 + r0 + 8) * RST + cc] =
                    make_float2(acc[mt][nt][2], acc[mt][nt][3]);
            }
        }
        __syncthreads();

        // 4-way reduce + LSTM epilogue: thread owns cells (eb, gu), (eb, gu+1)
        float gate[4][2];
        #pragma unroll
        for (int g = 0; g < 4; g++) {
            float2 s = make_float2(0.f, 0.f);
            #pragma unroll
            for (int k4 = 0; k4 < 4; k4++) {
                float2 v = *(const float2*)&red[(k4 * 64 + eb) * RST + g * 8 + 2 * eup];
                s.x += v.x; s.y += v.y;
            }
            gate[g][0] = s.x + xv[g][0] + breg[g][0];
            gate[g][1] = s.y + xv[g][1] + breg[g][1];
        }
        float hro[2], ho[2];
        #pragma unroll
        for (int j = 0; j < 2; j++) {
            float gi = 1.f / (1.f + expf(-gate[0][j]));
            float gf = 1.f / (1.f + expf(-gate[1][j]));
            float gc = tanhf(gate[2][j]);
            float go = 1.f / (1.f + expf(-gate[3][j]));
            float cn = fmaf(gf, creg[j], gi * gc);
            float hn = go * tanhf(cn);
            if (!is_dec && mv == 0.f) { hn = hreg[j]; cn = creg[j]; }
            creg[j] = cn;
            float hr = tf32r(hn);
            hreg[j] = hr;
            hro[j] = hr;
            ho[j]  = hn;
        }
        __stcg((float2*)(ht_out + (size_t)eb * NHID_D + gu), make_float2(hro[0], hro[1]));

        barrier_arrive((unsigned)(gstep + 1));   // h published; out stores overlap peers

        if (is_dec)
            *(float2*)(out + ((size_t)step * BATCH + eb) * NHID_D + gu) =
                make_float2(ho[0], ho[1]);
    }
}

// ---------------- launch ----------------------------------------------------
extern "C" void kernel_launch(void* const* d_in, const int* in_sizes, int n_in,
                              void* d_out, int out_size) {
    const float* input    = (const float*)d_in[0];  // [512,64,512]
    const float* mask     = (const float*)d_in[1];  // [512,64]
    const float* W_ih_enc = (const float*)d_in[2];  // [4096,512]
    const float* W_hh_enc = (const float*)d_in[3];  // [4096,1024]
    const float* b_ih_enc = (const float*)d_in[4];  // [4096]
    const float* b_hh_enc = (const float*)d_in[5];  // [4096]
    const float* W_ih_dec = (const float*)d_in[6];
    const float* W_hh_dec = (const float*)d_in[7];
    const float* b_ih_dec = (const float*)d_in[8];
    const float* b_hh_dec = (const float*)d_in[9];
    float* out = (float*)d_out;                     // [32768,1024]

    const int gemm_smem = 4 * GBUF * 4;                        // 73,728 B
    const int rnn_smem  = (32 * WST + 8 * 2 * TILEW) * 4;      // 205,312 B
    cudaFuncSetAttribute(gemm_xw_tc, cudaFuncAttributeMaxDynamicSharedMemorySize, gemm_smem);
    cudaFuncSetAttribute(rnn_persist, cudaFuncAttributeMaxDynamicSharedMemorySize, rnn_smem);

    init_state<<<(BATCH * NHID_D + 255) / 256, 256>>>();

    // rna pre-round of GEMM inputs (unbiased tf32)
    float* in_r  = nullptr; float* w0_r = nullptr; float* w1_r = nullptr;
    cudaGetSymbolAddress((void**)&in_r, g_in_r);
    cudaGetSymbolAddress((void**)&w0_r, g_wih_r);
    w1_r = w0_r + (size_t)NGATE * NINP_D;
    const int n4_in = T_STEPS * BATCH * NINP_D / 4;
    const int n4_w  = NGATE * NINP_D / 4;
    round_tf32_k<<<(n4_in + 255) / 256, 256>>>(input, in_r, n4_in);
    round_tf32_k<<<(n4_w + 255) / 256, 256>>>(W_ih_enc, w0_r, n4_w);
    round_tf32_k<<<(n4_w + 255) / 256, 256>>>(W_ih_dec, w1_r, n4_w);

    dim3 gg(NGATE / 128, (T_STEPS * BATCH) / 128);
    gemm_xw_tc<<<gg, 256, gemm_smem>>>(in_r, w0_r, b_ih_enc, 0);
    gemm_xw_tc<<<gg, 256, gemm_smem>>>(in_r, w1_r, b_ih_dec, 1);

    rnn_persist<<<NCTA_R, 256, rnn_smem>>>(W_hh_enc, W_hh_dec, b_hh_enc, b_hh_dec, mask, out);
}

// round 17
// speedup vs baseline: 1.1288x; 1.0304x over previous
#include <cuda_runtime.h>
#include <math.h>
#include <stdint.h>

#define T_STEPS 512
#define BATCH   64
#define NINP_D  512
#define NHID_D  1024
#define NGATE   4096   // 4*NHID
#define NCTA_R  128

// ---------------- scratch (device globals; no runtime allocation) ----------
__device__ float g_xw_enc[(size_t)T_STEPS * BATCH * NGATE]; // 512 MB
__device__ float g_xw_dec[(size_t)T_STEPS * BATCH * NGATE]; // 512 MB
__device__ float g_in_r[(size_t)T_STEPS * BATCH * NINP_D];  // rna-rounded input (64 MB)
__device__ float g_wih_r[2][(size_t)NGATE * NINP_D];        // rna-rounded W_ih (2x8 MB)
__device__ float g_h[2][BATCH * NHID_D];                    // h [b][u], tf32-rounded, ping-pong
__device__ unsigned g_arr1[128];   // group counters (stride 8 -> 32B apart)
__device__ unsigned g_root;
__device__ unsigned g_release;

// ---------------- generic helpers ------------------------------------------
__device__ __forceinline__ void cp_async16(unsigned s, const void* g) {
    asm volatile("cp.async.cg.shared.global [%0], [%1], 16;" :: "r"(s), "l"(g));
}
__device__ __forceinline__ void cp_commit() { asm volatile("cp.async.commit_group;"); }
__device__ __forceinline__ void cp_wait0()  { asm volatile("cp.async.wait_group 0;" ::: "memory"); }
__device__ __forceinline__ void cp_wait1()  { asm volatile("cp.async.wait_group 1;" ::: "memory"); }

__device__ __forceinline__ uint32_t tf32r_bits(float x) {
    uint32_t u; asm("cvt.rna.tf32.f32 %0, %1;" : "=r"(u) : "f"(x)); return u;
}
__device__ __forceinline__ float tf32r(float x) { return __uint_as_float(tf32r_bits(x)); }

// fast transcendentals: ex2.approx / rcp.approx (rel err ~2^-22, far below tf32 noise)
__device__ __forceinline__ float fast_ex2(float x) {
    float r; asm("ex2.approx.f32 %0, %1;" : "=f"(r) : "f"(x)); return r;
}
__device__ __forceinline__ float fast_rcp(float x) {
    float r; asm("rcp.approx.f32 %0, %1;" : "=f"(r) : "f"(x)); return r;
}
__device__ __forceinline__ float fsigmoid(float x) {
    // 1/(1+e^-x) = 1/(1+2^(-x*log2e))
    return fast_rcp(1.f + fast_ex2(-1.4426950408889634f * x));
}
__device__ __forceinline__ float ftanh(float x) {
    // tanh(x) = 2*sigmoid(2x) - 1
    return fmaf(2.f, fast_rcp(1.f + fast_ex2(-2.8853900817779268f * x)), -1.f);
}

// tf32 mma.sync (sm_80+, arch-portable): D[16x8] += A[16x8] * B[8x8]
__device__ __forceinline__ void mma_tf32(float& c0, float& c1, float& c2, float& c3,
                                         uint32_t a0, uint32_t a1, uint32_t a2, uint32_t a3,
                                         uint32_t b0, uint32_t b1) {
    asm("mma.sync.aligned.m16n8k8.row.col.f32.tf32.tf32.f32 "
        "{%0,%1,%2,%3}, {%4,%5,%6,%7}, {%8,%9}, {%0,%1,%2,%3};"
        : "+f"(c0), "+f"(c1), "+f"(c2), "+f"(c3)
        : "r"(a0), "r"(a1), "r"(a2), "r"(a3), "r"(b0), "r"(b1));
}

// ---------------- init ------------------------------------------------------
__global__ void init_state() {
    int i = blockIdx.x * blockDim.x + threadIdx.x;
    if (i == 0) { g_root = 0; g_release = 0; }
    if (i < 128) g_arr1[i] = 0;
    if (i < BATCH * NHID_D) { g_h[0][i] = 0.f; g_h[1][i] = 0.f; }
}

// ---------------- rna tf32 pre-round ---------------------------------------
__global__ __launch_bounds__(256) void round_tf32_k(const float* __restrict__ src,
                                                    float* __restrict__ dst, int n4) {
    int i = blockIdx.x * blockDim.x + threadIdx.x;
    if (i < n4) {
        float4 v = __ldg((const float4*)src + i);
        float4 o;
        o.x = tf32r(v.x); o.y = tf32r(v.y); o.z = tf32r(v.z); o.w = tf32r(v.w);
        ((float4*)dst)[i] = o;
    }
}

// ---------------- phase 1: xW = input @ W_ih^T + b_ih (tf32 mma.sync) ------
// CTA 128x128, k-chunk 32 dbuf, 8 warps (4m x 2n), warp tile 32x64. (validated)
#define AST 36
#define GBUF (128 * AST)

extern __shared__ float dynsm[];

__global__ __launch_bounds__(256) void gemm_xw_tc(const float* __restrict__ A,
                                                  const float* __restrict__ W,
                                                  const float* __restrict__ bias,
                                                  int which) {
    float* C = which ? g_xw_dec : g_xw_enc;
    unsigned abase = (unsigned)__cvta_generic_to_shared(dynsm);
    unsigned bbase = abase + 2u * GBUF * 4u;
    const uint32_t* Asw = (const uint32_t*)dynsm;
    const uint32_t* Bsw = Asw + 2 * GBUF;

    int t = threadIdx.x, lane = t & 31, wid = t >> 5;
    int gid = lane >> 2, tid = lane & 3;
    int wm = wid & 3, wn = wid >> 2;
    size_t m0 = (size_t)blockIdx.y * 128, n0 = (size_t)blockIdx.x * 128;

    float acc[2][8][4];
    #pragma unroll
    for (int mt = 0; mt < 2; mt++)
        #pragma unroll
        for (int nt = 0; nt < 8; nt++)
            #pragma unroll
            for (int r = 0; r < 4; r++) acc[mt][nt][r] = 0.f;

#define GFILL(kb, buf) do {                                                     \
        _Pragma("unroll")                                                       \
        for (int i_ = 0; i_ < 4; i_++) {                                        \
            int id_ = t + 256 * i_;                                             \
            int row_ = id_ >> 3, q_ = id_ & 7;                                  \
            cp_async16(abase + (unsigned)((buf) * GBUF + row_ * AST + q_ * 4) * 4, \
                       A + (m0 + row_) * NINP_D + (kb) * 32 + q_ * 4);          \
            cp_async16(bbase + (unsigned)((buf) * GBUF + row_ * AST + q_ * 4) * 4, \
                       W + (n0 + row_) * NINP_D + (kb) * 32 + q_ * 4);          \
        }                                                                       \
        cp_commit();                                                            \
    } while (0)

    GFILL(0, 0);
    #pragma unroll 1
    for (int kb = 0; kb < NINP_D / 32; kb++) {
        if (kb < NINP_D / 32 - 1) { GFILL(kb + 1, (kb + 1) & 1); cp_wait1(); }
        else cp_wait0();
        __syncthreads();
        const uint32_t* Ap = Asw + (kb & 1) * GBUF;
        const uint32_t* Bp = Bsw + (kb & 1) * GBUF;
        #pragma unroll
        for (int kk = 0; kk < 4; kk++) {
            int kl = kk * 8;
            uint32_t a[2][4], b[8][2];
            #pragma unroll
            for (int mt = 0; mt < 2; mt++) {
                int rb = wm * 32 + mt * 16;
                a[mt][0] = Ap[(rb + gid) * AST + kl + tid];
                a[mt][1] = Ap[(rb + gid + 8) * AST + kl + tid];
                a[mt][2] = Ap[(rb + gid) * AST + kl + tid + 4];
                a[mt][3] = Ap[(rb + gid + 8) * AST + kl + tid + 4];
            }
            #pragma unroll
            for (int nt = 0; nt < 8; nt++) {
                int rn = wn * 64 + nt * 8;
                b[nt][0] = Bp[(rn + gid) * AST + kl + tid];
                b[nt][1] = Bp[(rn + gid) * AST + kl + tid + 4];
            }
            #pragma unroll
            for (int mt = 0; mt < 2; mt++)
                #pragma unroll
                for (int nt = 0; nt < 8; nt++)
                    mma_tf32(acc[mt][nt][0], acc[mt][nt][1],
                             acc[mt][nt][2], acc[mt][nt][3],
                             a[mt][0], a[mt][1], a[mt][2], a[mt][3],
                             b[nt][0], b[nt][1]);
        }
        __syncthreads();
    }
#undef GFILL

    #pragma unroll
    for (int nt = 0; nt < 8; nt++) {
        int col = (int)n0 + wn * 64 + nt * 8 + 2 * tid;
        float2 bv = *(const float2*)&bias[col];
        #pragma unroll
        for (int mt = 0; mt < 2; mt++) {
            int r0 = wm * 32 + mt * 16 + gid;
            *(float2*)&C[(m0 + r0) * NGATE + col] =
                make_float2(acc[mt][nt][0] + bv.x, acc[mt][nt][1] + bv.y);
            *(float2*)&C[(m0 + r0 + 8) * NGATE + col] =
                make_float2(acc[mt][nt][2] + bv.x, acc[mt][nt][3] + bv.y);
        }
    }
}

// ---------------- two-level grid barrier (R12-validated, exact) --------------
__device__ __forceinline__ void barrier_arrive(unsigned target) {
    __threadfence();
    __syncthreads();
    if (threadIdx.x == 0) {
        int grp = blockIdx.x >> 3;
        unsigned prev = atomicAdd(&g_arr1[grp * 8], 1u);
        if (prev == target * 8u - 1u) {
            unsigned pr = atomicAdd(&g_root, 1u);
            if (pr == target * 16u - 1u) atomicExch(&g_release, target);
        }
    }
}
__device__ __forceinline__ void barrier_wait(unsigned target) {
    if (threadIdx.x == 0) {
        while (*(volatile unsigned*)&g_release < target) __nanosleep(32);
        __threadfence();
    }
    __syncthreads();
}

// ---------------- persistent tf32 mma.sync recurrence (R12 core, exact) -----
#define WST 1028
#define TST 36                    // warp tile row stride (words), ≡4 mod 32
#define TILEW (32 * TST)          // words per warp tile buffer (4608 B)
#define RST 34                    // reduce row stride (words)

__global__ __launch_bounds__(256) void rnn_persist(
        const float* __restrict__ W_enc, const float* __restrict__ W_dec,
        const float* __restrict__ bhh_enc, const float* __restrict__ bhh_dec,
        const float* __restrict__ mask, float* __restrict__ out) {
    float* wtile = dynsm;                 // [32][WST]
    float* atile = dynsm + 32 * WST;      // [8 warps][2 bufs][32][TST]
    float* red   = atile;                 // overlay: [4][64][RST]
    const uint32_t* wb = (const uint32_t*)wtile;

    int t = threadIdx.x, lane = t & 31, wid = t >> 5;
    int gid = lane >> 2, tid = lane & 3;
    int wm = wid >> 2, wk = wid & 3;
    int u0 = blockIdx.x * 8;
    int eb = t & 63, eup = t >> 6;
    int gu = u0 + 2 * eup;

    // warp-private tile base (smem address space)
    unsigned wtbase = (unsigned)__cvta_generic_to_shared(atile) + (unsigned)(wid * 2 * TILEW) * 4u;
    const uint32_t* wtw = (const uint32_t*)atile + wid * 2 * TILEW;
    int frow = (lane >> 3);               // fill: row group 0..3
    int fseg = (lane & 7);                // fill: 16B segment 0..7

    float creg[2] = {0.f, 0.f};
    float hreg[2] = {0.f, 0.f};
    float breg[4][2];

    for (int gstep = 0; gstep < 2 * T_STEPS; gstep++) {
        int is_dec = gstep >= T_STEPS;
        int step   = gstep & (T_STEPS - 1);
        const float* ht_in  = g_h[gstep & 1];
        float*       ht_out = g_h[(gstep + 1) & 1];
        const float* xw = (is_dec ? g_xw_dec : g_xw_enc) + (size_t)step * BATCH * NGATE;

        if (step == 0) {
            // W slice -> smem (tf32-rounded). smem row c = g*8+uu.  (validated)
            const float* Wh = is_dec ? W_dec : W_enc;
            int c  = t >> 3;
            int kb = (t & 7) * 128;
            const float* src = Wh + (size_t)((c >> 3) * NHID_D + u0 + (c & 7)) * NHID_D + kb;
            uint32_t* dst = (uint32_t*)(wtile + c * WST + kb);
            #pragma unroll 8
            for (int k = 0; k < 128; k += 4) {
                float4 v = __ldg((const float4*)(src + k));
                uint32_t x0 = tf32r_bits(v.x), x1 = tf32r_bits(v.y);
                uint32_t x2 = tf32r_bits(v.z), x3 = tf32r_bits(v.w);
                asm volatile("st.shared.v4.b32 [%0], {%1,%2,%3,%4};"
                             :: "l"(__cvta_generic_to_shared(dst + k)),
                                "r"(x0), "r"(x1), "r"(x2), "r"(x3));
            }
            #pragma unroll
            for (int g = 0; g < 4; g++) {
                const float* bh = is_dec ? bhh_dec : bhh_enc;
                float2 v = *(const float2*)(bh + g * NHID_D + gu);
                breg[g][0] = v.x; breg[g][1] = v.y;
            }
            __syncthreads();
        }

        // step-static prefetches (no h dependency) -> overlap with barrier wait
        float xv[4][2];
        #pragma unroll
        for (int g = 0; g < 4; g++) {
            float2 v = __ldcg((const float2*)(xw + (size_t)eb * NGATE + g * NHID_D + gu));
            xv[g][0] = v.x; xv[g][1] = v.y;
        }
        float mv = 1.f;
        if (!is_dec) mv = __ldg(&mask[(size_t)step * BATCH + eb]);

        barrier_wait((unsigned)gstep);

        float acc[2][4][4];
        #pragma unroll
        for (int mt = 0; mt < 2; mt++)
            #pragma unroll
            for (int nt = 0; nt < 4; nt++)
                #pragma unroll
                for (int r = 0; r < 4; r++) acc[mt][nt][r] = 0.f;

        // warp-private fill of own 32x32 tile for chunk ch into buffer buf
#define FILL_OWN(ch, buf) do {                                                   \
        const float* hsrc_ = ht_in + (size_t)(wm * 32) * NHID_D + (ch) * 128     \
                           + wk * 32 + fseg * 4;                                 \
        unsigned d0_ = wtbase + (unsigned)((buf) * TILEW + frow * TST + fseg * 4) * 4u; \
        _Pragma("unroll")                                                        \
        for (int i_ = 0; i_ < 8; i_++)                                           \
            cp_async16(d0_ + (unsigned)(i_ * 4 * TST) * 4u,                      \
                       hsrc_ + (size_t)(i_ * 4 + frow) * NHID_D);                \
        cp_commit();                                                             \
    } while (0)

        FILL_OWN(0, 0);
        #pragma unroll 1
        for (int c = 0; c < 8; c++) {
            if (c < 7) { FILL_OWN(c + 1, (c + 1) & 1); cp_wait1(); }
            else cp_wait0();
            __syncwarp();
            const uint32_t* tw = wtw + (c & 1) * TILEW;
            #pragma unroll
            for (int kk = 0; kk < 4; kk++) {
                int kl = kk * 8;                      // k within warp's 32-col tile
                int kgw = c * 128 + wk * 32 + kl;     // k in W tile
                uint32_t a[2][4], bf[4][2];
                #pragma unroll
                for (int mt = 0; mt < 2; mt++) {
                    int rl = mt * 16;                 // local row base
                    a[mt][0] = tw[(rl + gid) * TST + kl + tid];
                    a[mt][1] = tw[(rl + gid + 8) * TST + kl + tid];
                    a[mt][2] = tw[(rl + gid) * TST + kl + tid + 4];
                    a[mt][3] = tw[(rl + gid + 8) * TST + kl + tid + 4];
                }
                #pragma unroll
                for (int nt = 0; nt < 4; nt++) {
                    bf[nt][0] = wb[(nt * 8 + gid) * WST + kgw + tid];
                    bf[nt][1] = wb[(nt * 8 + gid) * WST + kgw + tid + 4];
                }
                #pragma unroll
                for (int mt = 0; mt < 2; mt++)
                    #pragma unroll
                    for (int nt = 0; nt < 4; nt++)
                        mma_tf32(acc[mt][nt][0], acc[mt][nt][1],
                                 acc[mt][nt][2], acc[mt][nt][3],
                                 a[mt][0], a[mt][1], a[mt][2], a[mt][3],
                                 bf[nt][0], bf[nt][1]);
            }
        }
#undef FILL_OWN

        __syncthreads();              // all warps' mma reads done before red overlay

        // store k-partials (overlay on A-tile region)
        #pragma unroll
        for (int mt = 0; mt < 2; mt++) {
            int r0 = wm * 32 + mt * 16 + gid;
            #pragma unroll
            for (int nt = 0; nt < 4; nt++) {
                int cc = nt * 8 + 2 * tid;
                *(float2*)&red[(wk * 64 + r0) * RST + cc] =
                    make_float2(acc[mt][nt][0], acc[mt][nt][1]);
                *(float2*)&red[(wk * 64 + r0 + 8) * RST + cc] =
                    make_float2(acc[mt][nt][2], acc[mt][nt][3]);
            }
        }
        __syncthreads();

        // 4-way reduce + LSTM epilogue: thread owns cells (eb, gu), (eb, gu+1)
        float gate[4][2];
        #pragma unroll
        for (int g = 0; g < 4; g++) {
            float2 s = make_float2(0.f, 0.f);
            #pragma unroll
            for (int k4 = 0; k4 < 4; k4++) {
                float2 v = *(const float2*)&red[(k4 * 64 + eb) * RST + g * 8 + 2 * eup];
                s.x += v.x; s.y += v.y;
            }
            gate[g][0] = s.x + xv[g][0] + breg[g][0];
            gate[g][1] = s.y + xv[g][1] + breg[g][1];
        }
        float hro[2], ho[2];
        #pragma unroll
        for (int j = 0; j < 2; j++) {
            float gi = fsigmoid(gate[0][j]);
            float gf = fsigmoid(gate[1][j]);
            float gc = ftanh(gate[2][j]);
            float go = fsigmoid(gate[3][j]);
            float cn = fmaf(gf, creg[j], gi * gc);
            float hn = go * ftanh(cn);
            if (!is_dec && mv == 0.f) { hn = hreg[j]; cn = creg[j]; }
            creg[j] = cn;
            float hr = tf32r(hn);
            hreg[j] = hr;
            hro[j] = hr;
            ho[j]  = hn;
        }
        __stcg((float2*)(ht_out + (size_t)eb * NHID_D + gu), make_float2(hro[0], hro[1]));

        barrier_arrive((unsigned)(gstep + 1));   // h published; out stores overlap peers

        if (is_dec)
            *(float2*)(out + ((size_t)step * BATCH + eb) * NHID_D + gu) =
                make_float2(ho[0], ho[1]);
    }
}

// ---------------- launch ----------------------------------------------------
extern "C" void kernel_launch(void* const* d_in, const int* in_sizes, int n_in,
                              void* d_out, int out_size) {
    const float* input    = (const float*)d_in[0];  // [512,64,512]
    const float* mask     = (const float*)d_in[1];  // [512,64]
    const float* W_ih_enc = (const float*)d_in[2];  // [4096,512]
    const float* W_hh_enc = (const float*)d_in[3];  // [4096,1024]
    const float* b_ih_enc = (const float*)d_in[4];  // [4096]
    const float* b_hh_enc = (const float*)d_in[5];  // [4096]
    const float* W_ih_dec = (const float*)d_in[6];
    const float* W_hh_dec = (const float*)d_in[7];
    const float* b_ih_dec = (const float*)d_in[8];
    const float* b_hh_dec = (const float*)d_in[9];
    float* out = (float*)d_out;                     // [32768,1024]

    const int gemm_smem = 4 * GBUF * 4;                        // 73,728 B
    const int rnn_smem  = (32 * WST + 8 * 2 * TILEW) * 4;      // 205,312 B
    cudaFuncSetAttribute(gemm_xw_tc, cudaFuncAttributeMaxDynamicSharedMemorySize, gemm_smem);
    cudaFuncSetAttribute(rnn_persist, cudaFuncAttributeMaxDynamicSharedMemorySize, rnn_smem);

    init_state<<<(BATCH * NHID_D + 255) / 256, 256>>>();

    // rna pre-round of GEMM inputs (unbiased tf32)
    float* in_r  = nullptr; float* w0_r = nullptr; float* w1_r = nullptr;
    cudaGetSymbolAddress((void**)&in_r, g_in_r);
    cudaGetSymbolAddress((void**)&w0_r, g_wih_r);
    w1_r = w0_r + (size_t)NGATE * NINP_D;
    const int n4_in = T_STEPS * BATCH * NINP_D / 4;
    const int n4_w  = NGATE * NINP_D / 4;
    round_tf32_k<<<(n4_in + 255) / 256, 256>>>(input, in_r, n4_in);
    round_tf32_k<<<(n4_w + 255) / 256, 256>>>(W_ih_enc, w0_r, n4_w);
    round_tf32_k<<<(n4_w + 255) / 256, 256>>>(W_ih_dec, w1_r, n4_w);

    dim3 gg(NGATE / 128, (T_STEPS * BATCH) / 128);
    gemm_xw_tc<<<gg, 256, gemm_smem>>>(in_r, w0_r, b_ih_enc, 0);
    gemm_xw_tc<<<gg, 256, gemm_smem>>>(in_r, w1_r, b_ih_dec, 1);

    rnn_persist<<<NCTA_R, 256, rnn_smem>>>(W_hh_enc, W_hh_dec, b_hh_enc, b_hh_dec, mask, out);
}